// round 15
// baseline (speedup 1.0000x reference)
#include <cuda_runtime.h>
#include <cuda_bf16.h>
#include <cuda_fp16.h>
#include <cstdint>

#define FULL_MASK 0xFFFFFFFFu

// ------------------------- device scratch ----------------------------------
__device__ float g_u[512 * 4];
__device__ float g_c1[4];
__device__ float g_dpart[2048 * 4];
__device__ float g_spart[1024 * 2048];
__device__ float g_spart2[16 * 2048];
__device__ float g_x1[512];
__device__ float g_x2[512];
__device__ float g_qk[1024];
__device__ float g_U[512 * 4];
__device__ float g_c[4];
__device__ float g_vals[512];
__device__ float g_sv[4];
__device__ float g_svv[4];
// Wm^T in fp16, chunk-major: [kchunk64][n][kk]
__device__ __half g_WmB[512 * 512];

// ------------------------- helpers -----------------------------------------
__device__ __forceinline__ unsigned long long pack2(float lo, float hi) {
    unsigned long long r;
    asm("mov.b64 %0, {%1, %2};" : "=l"(r) : "f"(lo), "f"(hi));
    return r;
}
__device__ __forceinline__ void unpack2(unsigned long long v, float& lo, float& hi) {
    asm("mov.b64 {%0, %1}, %2;" : "=f"(lo), "=f"(hi) : "l"(v));
}
__device__ __forceinline__ void fma2(unsigned long long& acc,
                                     unsigned long long a, unsigned long long b) {
    asm("fma.rn.f32x2 %0, %1, %2, %0;" : "+l"(acc) : "l"(a), "l"(b));
}
__device__ __forceinline__ float silu_fast(float x) {
    return __fdividef(x, 1.0f + __expf(-x));
}
__device__ __forceinline__ uint32_t smem_u32(const void* p) {
    uint32_t a;
    asm("{ .reg .u64 t; cvta.to.shared.u64 t, %1; cvt.u32.u64 %0, t; }" : "=r"(a) : "l"(p));
    return a;
}
__device__ __forceinline__ uint32_t pkh(__half a, __half b) {
    return (uint32_t)__half_as_ushort(a) | ((uint32_t)__half_as_ushort(b) << 16);
}
__device__ __forceinline__ void cp16(uint32_t dst, const void* src) {
    asm volatile("cp.async.cg.shared.global [%0], [%1], 16;" :: "r"(dst), "l"(src));
}
__device__ __forceinline__ void ldsm4(uint32_t& r0, uint32_t& r1, uint32_t& r2,
                                      uint32_t& r3, uint32_t addr) {
    asm volatile("ldmatrix.sync.aligned.m8n8.x4.shared.b16 {%0,%1,%2,%3}, [%4];"
                 : "=r"(r0), "=r"(r1), "=r"(r2), "=r"(r3) : "r"(addr));
}
__device__ __forceinline__ void mma_f16(float& d0, float& d1, float& d2, float& d3,
                                        uint32_t a0, uint32_t a1, uint32_t a2, uint32_t a3,
                                        uint32_t b0, uint32_t b1) {
    asm volatile(
        "mma.sync.aligned.m16n8k16.row.col.f32.f16.f16.f32 "
        "{%0,%1,%2,%3}, {%4,%5,%6,%7}, {%8,%9}, {%0,%1,%2,%3};"
        : "+f"(d0), "+f"(d1), "+f"(d2), "+f"(d3)
        : "r"(a0), "r"(a1), "r"(a2), "r"(a3), "r"(b0), "r"(b1));
}

// ------------------------- kernel: prep fused (Wm fp16 + Wq/rk fold) --------
__global__ void __launch_bounds__(1024) k_prepF(const float* __restrict__ Wm,
                                                const float* __restrict__ Wq,
                                                const float* __restrict__ bq,
                                                const float* __restrict__ rk) {
    if (blockIdx.x == 16) {
        if (blockIdx.y == 0) {
            int t = threadIdx.y * 32 + threadIdx.x;
            if (t < 512) {
                float u[4];
#pragma unroll
                for (int r = 0; r < 4; r++) {
                    float s = 0.f;
#pragma unroll
                    for (int d = 0; d < 4; d++) s += Wq[t * 16 + 4 * r + d] * rk[4 * r + d];
                    u[r] = s;
                }
                ((float4*)g_u)[t] = make_float4(u[0], u[1], u[2], u[3]);
                if (t < 4) {
                    float s = 0.f;
#pragma unroll
                    for (int d = 0; d < 4; d++) s += bq[4 * t + d] * rk[4 * t + d];
                    g_c1[t] = s;
                }
            }
        }
        return;
    }
    __shared__ float tile[32][33];
    int tx = threadIdx.x, ty = threadIdx.y;
    tile[ty][tx] = Wm[(blockIdx.y * 32 + ty) * 512 + blockIdx.x * 32 + tx];
    __syncthreads();
    int n = blockIdx.x * 32 + ty;
    int k = blockIdx.y * 32 + tx;
    float v = tile[tx][ty];
    size_t idx = ((size_t)(k >> 6) * 512 + n) * 64 + (k & 63);
    g_WmB[idx] = __float2half(v);
}

// ------------------------- kernel: fused pass 1 -----------------------------
__global__ void __launch_bounds__(512) k_pass1(const float* __restrict__ h, int n) {
    __shared__ float4 se[128];
    __shared__ float sD[16][4];
    const int tid = threadIdx.x, warp = tid >> 5, lane = tid & 31;
    const int base = blockIdx.x * 128;

    const float c10 = g_c1[0], c11 = g_c1[1], c12 = g_c1[2], c13 = g_c1[3];
    float d0 = 0.f, d1 = 0.f, d2 = 0.f, d3 = 0.f;

#pragma unroll
    for (int rr = 0; rr < 8; rr++) {
        const int rloc = warp * 8 + rr;
        const int row = base + rloc;
        const bool valid = (row < n);
        const float* hr = h + (size_t)row * 512;

        float l0 = 0.f, l1 = 0.f, l2 = 0.f, l3 = 0.f;
        if (valid) {
#pragma unroll
            for (int t = 0; t < 16; t++) {
                int k = lane + 32 * t;
                float hk = __ldg(hr + k);
                float4 u = __ldg((const float4*)g_u + k);
                l0 += hk * u.x; l1 += hk * u.y; l2 += hk * u.z; l3 += hk * u.w;
            }
        }
#pragma unroll
        for (int o = 16; o; o >>= 1) {
            l0 += __shfl_xor_sync(FULL_MASK, l0, o);
            l1 += __shfl_xor_sync(FULL_MASK, l1, o);
            l2 += __shfl_xor_sync(FULL_MASK, l2, o);
            l3 += __shfl_xor_sync(FULL_MASK, l3, o);
        }
        if (lane == 0) {
            float m = valid ? 1.f : 0.f;
            float e0 = m * __expf(0.5f * (l0 + c10));
            float e1 = m * __expf(0.5f * (l1 + c11));
            float e2 = m * __expf(0.5f * (l2 + c12));
            float e3 = m * __expf(0.5f * (l3 + c13));
            se[rloc] = make_float4(e0, e1, e2, e3);
            d0 += e0; d1 += e1; d2 += e2; d3 += e3;
        }
    }
    if (lane == 0) {
        sD[warp][0] = d0; sD[warp][1] = d1; sD[warp][2] = d2; sD[warp][3] = d3;
    }
    __syncthreads();
    if (warp == 0 && lane < 4) {
        float s = 0.f;
#pragma unroll
        for (int w = 0; w < 16; w++) s += sD[w][lane];
        g_dpart[blockIdx.x * 4 + lane] = s;
    }

    const int c = tid;
    int lim = n - base; if (lim > 128) lim = 128;
    unsigned long long a01 = pack2(0.f, 0.f), a23 = pack2(0.f, 0.f);
    const float* hc = h + (size_t)base * 512 + c;
#pragma unroll 4
    for (int i = 0; i < lim; i++) {
        float4 e = se[i];
        float hv = __ldg(hc + (size_t)i * 512);
        unsigned long long hd = pack2(hv, hv);
        fma2(a01, hd, pack2(e.x, e.y));
        fma2(a23, hd, pack2(e.z, e.w));
    }
    float s0, s1, s2, s3;
    unpack2(a01, s0, s1);
    unpack2(a23, s2, s3);
    float* dst = g_spart + (size_t)blockIdx.x * 2048;
    dst[0 * 512 + c] = s0;
    dst[1 * 512 + c] = s1;
    dst[2 * 512 + c] = s2;
    dst[3 * 512 + c] = s3;
}

// ------------------------- kernel: S partial reduction (grid 4x16) ----------
__global__ void __launch_bounds__(512) k_redS(int nb) {
    const int col = blockIdx.x * 512 + threadIdx.x;
    const int chunk = (nb + 15) / 16;
    int i0 = blockIdx.y * chunk;
    int i1 = i0 + chunk; if (i1 > nb) i1 = nb;
    float s = 0.f;
    const float* src = g_spart + col;
#pragma unroll 4
    for (int i = i0; i < i1; i++) s += src[(size_t)i * 2048];
    g_spart2[blockIdx.y * 2048 + col] = s;
}

// ------------------------- kernel: smallA (S/D finalize, LN chain, x1) ------
__global__ void __launch_bounds__(512) k_smallA(int nb,
        const float* __restrict__ Wv,  const float* __restrict__ bv,
        const float* __restrict__ lrs, const float* __restrict__ lrb,
        const float* __restrict__ l1s, const float* __restrict__ l1b,
        const float* __restrict__ W1,  const float* __restrict__ b1) {
    __shared__ float sS[4 * 512];
    __shared__ float sDv[4];
    __shared__ float sNum[16];
    __shared__ float sr16[16];
    const int tid = threadIdx.x, warp = tid >> 5, lane = tid & 31;

#pragma unroll
    for (int r = 0; r < 4; r++) {
        int col = r * 512 + tid;
        float s = 0.f;
#pragma unroll
        for (int j = 0; j < 16; j++) s += g_spart2[j * 2048 + col];
        sS[col] = s;
    }
    if (warp < 4) {
        float s = 0.f;
        for (int i = lane; i < nb; i += 32) s += g_dpart[i * 4 + warp];
#pragma unroll
        for (int o = 16; o; o >>= 1) s += __shfl_xor_sync(FULL_MASK, s, o);
        if (lane == 0) sDv[warp] = s;
    }
    __syncthreads();

    {
        const int r = warp >> 2;
        float s = 0.f;
        for (int c = lane; c < 512; c += 32) s += sS[r * 512 + c] * Wv[c * 16 + warp];
#pragma unroll
        for (int o = 16; o; o >>= 1) s += __shfl_xor_sync(FULL_MASK, s, o);
        if (lane == 0) sNum[warp] = s;
    }
    __syncthreads();

    if (tid == 0) {
        float reg[16];
#pragma unroll
        for (int i = 0; i < 16; i++) reg[i] = sNum[i] / sDv[i >> 2] + bv[i];
#pragma unroll
        for (int pass = 0; pass < 2; pass++) {
            const float* sc = pass ? l1s : lrs;
            const float* bc = pass ? l1b : lrb;
            float m = 0.f;
            for (int i = 0; i < 16; i++) m += reg[i];
            m *= (1.f / 16.f);
            float v = 0.f;
            for (int i = 0; i < 16; i++) { float d = reg[i] - m; v += d * d; }
            v *= (1.f / 16.f);
            float inv = rsqrtf(v + 1e-6f);
            for (int i = 0; i < 16; i++) reg[i] = (reg[i] - m) * inv * sc[i] + bc[i];
        }
        for (int i = 0; i < 16; i++) sr16[i] = reg[i];
    }
    __syncthreads();

    float s = b1[tid];
#pragma unroll
    for (int i = 0; i < 16; i++) s += sr16[i] * W1[i * 512 + tid];
    g_x1[tid] = s / (1.f + expf(-s));
}

// ------------------------- kernel: smallB2 — x2 (grid 8) --------------------
__global__ void __launch_bounds__(512) k_smallB2(const float* __restrict__ W2,
                                                 const float* __restrict__ b2) {
    __shared__ float sx1[512];
    __shared__ float red[512];
    const int t = threadIdx.x;
    sx1[t] = g_x1[t];
    __syncthreads();
    const int j = blockIdx.x * 64 + (t & 63);
    const int ks = t >> 6;
    float s = 0.f;
    const float* w = W2 + (size_t)(ks * 64) * 512 + j;
    const float* xs = sx1 + ks * 64;
#pragma unroll 16
    for (int k = 0; k < 64; k++) s += xs[k] * __ldg(w + (size_t)k * 512);
    red[t] = s;
    __syncthreads();
    if (t < 64) {
        float v = b2[blockIdx.x * 64 + t];
#pragma unroll
        for (int i = 0; i < 8; i++) v += red[i * 64 + t];
        g_x2[blockIdx.x * 64 + t] = v / (1.f + expf(-v));
    }
}

// ------------------------- kernel: smallC2 — qk (grid 16) -------------------
__global__ void __launch_bounds__(512) k_smallC2(const float* __restrict__ W3,
                                                 const float* __restrict__ b3) {
    __shared__ float sx2[512];
    __shared__ float red[512];
    const int t = threadIdx.x;
    sx2[t] = g_x2[t];
    __syncthreads();
    const int j = blockIdx.x * 64 + (t & 63);
    const int ks = t >> 6;
    float s = 0.f;
    const float* w = W3 + (size_t)(ks * 64) * 1024 + j;
    const float* xs = sx2 + ks * 64;
#pragma unroll 16
    for (int k = 0; k < 64; k++) s += xs[k] * __ldg(w + (size_t)k * 1024);
    red[t] = s;
    __syncthreads();
    if (t < 64) {
        float v = b3[blockIdx.x * 64 + t];
#pragma unroll
        for (int i = 0; i < 8; i++) v += red[i * 64 + t];
        g_qk[blockIdx.x * 64 + t] = v;
    }
}

// ------------------------- kernel: smallD2 — U fold + stats (grid 9) --------
__global__ void __launch_bounds__(512) k_smallD2(const float* __restrict__ Wk,
                                                 const float* __restrict__ bk) {
    const int t = threadIdx.x, warp = t >> 5, lane = t & 31;
    if (blockIdx.x == 8) {
        g_vals[t] = g_qk[512 + t];
        if (warp < 4) {
            float s = 0.f, sv = 0.f, svv = 0.f;
            for (int d = lane; d < 128; d += 32) {
                float qv = g_qk[warp * 128 + d];
                s += bk[warp * 128 + d] * qv;
                float v = g_qk[512 + warp * 128 + d];
                sv += v; svv += v * v;
            }
#pragma unroll
            for (int o = 16; o; o >>= 1) {
                s   += __shfl_xor_sync(FULL_MASK, s, o);
                sv  += __shfl_xor_sync(FULL_MASK, sv, o);
                svv += __shfl_xor_sync(FULL_MASK, svv, o);
            }
            if (lane == 0) {
                g_c[warp] = s * rsqrtf(128.f);
                g_sv[warp] = sv;
                g_svv[warp] = svv;
            }
        }
        return;
    }
    __shared__ float sqk[1024];
    __shared__ float red[512];
    sqk[t] = g_qk[t];
    sqk[t + 512] = g_qk[t + 512];
    __syncthreads();
    const int r = blockIdx.x * 64 + (t >> 3);
    const int p = t & 7, head = p >> 1, half = p & 1;
    const float4* wr = (const float4*)(Wk + (size_t)r * 512 + head * 128 + half * 64);
    const float* qv = sqk + head * 128 + half * 64;
    float s = 0.f;
#pragma unroll
    for (int d4 = 0; d4 < 16; d4++) {
        float4 w = __ldg(wr + d4);
        s += w.x * qv[4 * d4 + 0] + w.y * qv[4 * d4 + 1]
           + w.z * qv[4 * d4 + 2] + w.w * qv[4 * d4 + 3];
    }
    red[t] = s;
    __syncthreads();
    if (t < 256) {
        const int rr = t >> 2, hh = t & 3;
        float v = red[rr * 8 + hh * 2] + red[rr * 8 + hh * 2 + 1];
        g_U[(blockIdx.x * 64 + rr) * 4 + hh] = v * rsqrtf(128.f);
    }
}

// ------------------------- kernel: main (HMMA fp16, 32-row CTA, 2/SM) -------
// Block: 32 rows x 512 cols, 512 threads (16 warps; warp tile 32 rows x 32 cols).
// A (h2n fp16, full K) in smem; B single-buffered Kc=64; register epilogue.
#define BSTRIDE 144
#define ASTRIDE 1040
#define OFF_A 73728
#define OFF_SA 107008
#define OFF_MEAN 107520
#define OFF_INV 107648
#define SMEM_DYN 107904

__device__ __forceinline__ void loadB_async(uint32_t base32, int kc, int tid) {
    const __half* sH = g_WmB + (size_t)kc * 32768;
#pragma unroll
    for (int j = 0; j < 8; j++) {
        int f = j * 512 + tid;
        uint32_t doff = (uint32_t)((f >> 3) * BSTRIDE + (f & 7) * 16);
        cp16(base32 + doff, sH + f * 8);
    }
}

__global__ void __launch_bounds__(512, 2) k_main_mma(const float* __restrict__ h,
        const float* __restrict__ ln2s, const float* __restrict__ ln2b,
        const float* __restrict__ bm,
        const float* __restrict__ ln3s, const float* __restrict__ ln3b,
        float* __restrict__ out, int n) {
    extern __shared__ char sb[];
    const uint32_t base32 = smem_u32(sb);
    float* sa    = (float*)(sb + OFF_SA);     // [32][4]
    float* smean = (float*)(sb + OFF_MEAN);   // [32]
    float* sinv  = (float*)(sb + OFF_INV);    // [32]
    float* red   = (float*)sb;                // epilogue: [32][16] x2 (B region)

    const int tid = threadIdx.x, warp = tid >> 5, lane = tid & 31;
    const int row0 = blockIdx.x * 32;

    // ---------- Phase A: per-row softmax + closed-form LN2 stats (2 rows/warp)
    {
        const float c0 = g_c[0], c1 = g_c[1], c2 = g_c[2], c3 = g_c[3];
        const float sv0 = g_sv[0], sv1 = g_sv[1], sv2 = g_sv[2], sv3 = g_sv[3];
        const float w0 = g_svv[0], w1 = g_svv[1], w2 = g_svv[2], w3 = g_svv[3];
#pragma unroll
        for (int rr = 0; rr < 2; rr++) {
            const int rloc = warp * 2 + rr;
            const int row = row0 + rloc;
            const bool valid = (row < n);
            const float* hr = h + (size_t)row * 512;
            float l0 = 0.f, l1 = 0.f, l2 = 0.f, l3 = 0.f;
            float hv0 = 0.f, hv1 = 0.f, hv2 = 0.f, hv3 = 0.f;
            float sh = 0.f, sq = 0.f;
            if (valid) {
#pragma unroll
                for (int t = 0; t < 16; t++) {
                    int k = lane + 32 * t;
                    float hk = __ldg(hr + k);
                    float4 u = __ldg((const float4*)g_U + k);
                    float vk = __ldg(g_vals + k);
                    l0 += hk * u.x; l1 += hk * u.y; l2 += hk * u.z; l3 += hk * u.w;
                    float p = hk * vk;
                    if (t < 4) hv0 += p; else if (t < 8) hv1 += p;
                    else if (t < 12) hv2 += p; else hv3 += p;
                    sh += hk; sq += hk * hk;
                }
            }
#pragma unroll
            for (int o = 16; o; o >>= 1) {
                l0 += __shfl_xor_sync(FULL_MASK, l0, o);
                l1 += __shfl_xor_sync(FULL_MASK, l1, o);
                l2 += __shfl_xor_sync(FULL_MASK, l2, o);
                l3 += __shfl_xor_sync(FULL_MASK, l3, o);
                hv0 += __shfl_xor_sync(FULL_MASK, hv0, o);
                hv1 += __shfl_xor_sync(FULL_MASK, hv1, o);
                hv2 += __shfl_xor_sync(FULL_MASK, hv2, o);
                hv3 += __shfl_xor_sync(FULL_MASK, hv3, o);
                sh += __shfl_xor_sync(FULL_MASK, sh, o);
                sq += __shfl_xor_sync(FULL_MASK, sq, o);
            }
            if (lane == 0) {
                if (valid) {
                    l0 += c0; l1 += c1; l2 += c2; l3 += c3;
                    float mx = fmaxf(fmaxf(l0, l1), fmaxf(l2, l3));
                    float e0 = __expf(l0 - mx), e1 = __expf(l1 - mx);
                    float e2 = __expf(l2 - mx), e3 = __expf(l3 - mx);
                    float si = __fdividef(1.f, e0 + e1 + e2 + e3);
                    float a0 = e0 * si, a1 = e1 * si, a2 = e2 * si, a3 = e3 * si;
                    float sum = sh + a0 * sv0 + a1 * sv1 + a2 * sv2 + a3 * sv3;
                    float ssq = sq + 2.f * (a0 * hv0 + a1 * hv1 + a2 * hv2 + a3 * hv3)
                              + a0 * a0 * w0 + a1 * a1 * w1 + a2 * a2 * w2 + a3 * a3 * w3;
                    float mean = sum * (1.f / 512.f);
                    float var = ssq * (1.f / 512.f) - mean * mean;
                    sa[rloc * 4 + 0] = a0; sa[rloc * 4 + 1] = a1;
                    sa[rloc * 4 + 2] = a2; sa[rloc * 4 + 3] = a3;
                    smean[rloc] = mean;
                    sinv[rloc] = rsqrtf(var + 1e-6f);
                } else {
                    sa[rloc * 4 + 0] = 0.f; sa[rloc * 4 + 1] = 0.f;
                    sa[rloc * 4 + 2] = 0.f; sa[rloc * 4 + 3] = 0.f;
                    smean[rloc] = 0.f; sinv[rloc] = 0.f;
                }
            }
        }
    }
    __syncthreads();

    // ---------- Build full A tile (h2n fp16, K=512): 16 threads/row ----------
    {
        const int arow = tid >> 4, kq = tid & 15;   // k span [kq*32, kq*32+32)
        const bool avalid = (row0 + arow < n);
        const float* harow = h + (size_t)(row0 + arow) * 512;
        const float mean = smean[arow], inv = sinv[arow];
        const float ah = sa[arow * 4 + (kq >> 2)];  // head = (kq*32)>>7 = kq>>2
        char* arb = sb + OFF_A + arow * ASTRIDE;
#pragma unroll
        for (int j = 0; j < 4; j++) {
            const int kg = kq * 32 + j * 8;
            float4 hv0 = make_float4(0.f, 0.f, 0.f, 0.f), hv1 = hv0;
            if (avalid) {
                hv0 = __ldg((const float4*)(harow + kg));
                hv1 = __ldg((const float4*)(harow + kg + 4));
            }
            float4 vA = __ldg((const float4*)(g_vals + kg));
            float4 vB = __ldg((const float4*)(g_vals + kg + 4));
            float4 sA = __ldg((const float4*)(ln2s + kg));
            float4 sB = __ldg((const float4*)(ln2s + kg + 4));
            float4 bA = __ldg((const float4*)(ln2b + kg));
            float4 bB = __ldg((const float4*)(ln2b + kg + 4));
            float hx[8] = {hv0.x, hv0.y, hv0.z, hv0.w, hv1.x, hv1.y, hv1.z, hv1.w};
            float vx[8] = {vA.x, vA.y, vA.z, vA.w, vB.x, vB.y, vB.z, vB.w};
            float sx[8] = {sA.x, sA.y, sA.z, sA.w, sB.x, sB.y, sB.z, sB.w};
            float bx[8] = {bA.x, bA.y, bA.z, bA.w, bB.x, bB.y, bB.z, bB.w};
            uint32_t w[4];
#pragma unroll
            for (int p = 0; p < 4; p++) {
                float x0 = avalid ? ((hx[2 * p] + ah * vx[2 * p] - mean) * inv * sx[2 * p] + bx[2 * p]) : 0.f;
                float x1 = avalid ? ((hx[2 * p + 1] + ah * vx[2 * p + 1] - mean) * inv * sx[2 * p + 1] + bx[2 * p + 1]) : 0.f;
                w[p] = pkh(__float2half(x0), __float2half(x1));
            }
            *(uint4*)(arb + kg * 2) = make_uint4(w[0], w[1], w[2], w[3]);
        }
    }
    __syncthreads();

    // ---------- GEMM: 8 chunks of Kc=64, B single-buffered -------------------
    const int g = lane >> 2, tig = lane & 3;
    const uint32_t aoff = (uint32_t)((lane & 15) * ASTRIDE + (lane >> 4) * 16);
    const uint32_t boff = (uint32_t)(((((lane >> 4) << 3) + (lane & 7)) * BSTRIDE)
                                     + ((lane >> 3) & 1) * 16);
    const uint32_t aAddr = base32 + OFF_A + aoff;                       // rows 0..31
    const uint32_t bAddr = base32 + (uint32_t)(warp * 32) * BSTRIDE + boff;  // cols warp*32..

    float d[2][4][4];
#pragma unroll
    for (int m = 0; m < 2; m++)
#pragma unroll
        for (int q = 0; q < 4; q++)
#pragma unroll
            for (int e = 0; e < 4; e++) d[m][q][e] = 0.f;

    for (int kc = 0; kc < 8; kc++) {
        loadB_async(base32, kc, tid);
        asm volatile("cp.async.commit_group;" ::: "memory");
        asm volatile("cp.async.wait_group 0;" ::: "memory");
        __syncthreads();

#pragma unroll
        for (int ks = 0; ks < 4; ks++) {
            const uint32_t ka = aAddr + (uint32_t)(kc * 128 + ks * 32);
            uint32_t ah[8];
            ldsm4(ah[0], ah[1], ah[2], ah[3], ka);
            ldsm4(ah[4], ah[5], ah[6], ah[7], ka + 16 * ASTRIDE);
            const uint32_t kb = bAddr + (uint32_t)(ks * 32);
            uint32_t bh[8];
            ldsm4(bh[0], bh[1], bh[2], bh[3], kb);
            ldsm4(bh[4], bh[5], bh[6], bh[7], kb + 16 * BSTRIDE);
#pragma unroll
            for (int q = 0; q < 4; q++) {
                const uint32_t b0 = bh[(q >> 1) * 4 + 2 * (q & 1)];
                const uint32_t b1 = bh[(q >> 1) * 4 + 2 * (q & 1) + 1];
                mma_f16(d[0][q][0], d[0][q][1], d[0][q][2], d[0][q][3],
                        ah[0], ah[1], ah[2], ah[3], b0, b1);
                mma_f16(d[1][q][0], d[1][q][1], d[1][q][2], d[1][q][3],
                        ah[4], ah[5], ah[6], ah[7], b0, b1);
            }
        }
        __syncthreads();   // all warps done with B before next chunk overwrites
    }

    // ---------- register epilogue: y, LN3, write -----------------------------
    {
        // thread rows: m*16 + rh*8 + g (m,rh in {0,1}); cols: warp*32 + q*8 + 2*tig
        float rsum[4], rsq[4];
#pragma unroll
        for (int i = 0; i < 4; i++) { rsum[i] = 0.f; rsq[i] = 0.f; }
#pragma unroll
        for (int m = 0; m < 2; m++) {
#pragma unroll
            for (int q = 0; q < 4; q++) {
                const int c = warp * 32 + q * 8 + 2 * tig;
                float2 bmv = __ldg((const float2*)(bm + c));
#pragma unroll
                for (int rh = 0; rh < 2; rh++) {
                    const int rowl = m * 16 + rh * 8 + g;
                    float2 a2 = __half22float2(
                        *(const __half2*)(sb + OFF_A + rowl * ASTRIDE + c * 2));
                    float y0 = a2.x + silu_fast(d[m][q][2 * rh] + bmv.x);
                    float y1 = a2.y + silu_fast(d[m][q][2 * rh + 1] + bmv.y);
                    d[m][q][2 * rh] = y0;
                    d[m][q][2 * rh + 1] = y1;
                    rsum[m * 2 + rh] += y0 + y1;
                    rsq[m * 2 + rh] += y0 * y0 + y1 * y1;
                }
            }
        }
        // reduce across the 4 tig lanes (same rows)
#pragma unroll
        for (int i = 0; i < 4; i++) {
            rsum[i] += __shfl_xor_sync(FULL_MASK, rsum[i], 1);
            rsum[i] += __shfl_xor_sync(FULL_MASK, rsum[i], 2);
            rsq[i]  += __shfl_xor_sync(FULL_MASK, rsq[i], 1);
            rsq[i]  += __shfl_xor_sync(FULL_MASK, rsq[i], 2);
        }
        if (tig == 0) {
#pragma unroll
            for (int i = 0; i < 4; i++) {
                const int rowl = (i >> 1) * 16 + (i & 1) * 8 + g;
                red[rowl * 16 + warp] = rsum[i];
                red[512 + rowl * 16 + warp] = rsq[i];
            }
        }
        __syncthreads();

        // per-row stats: warp handles rows 2*warp, 2*warp+1 (16 lanes each)
        {
            const int rowl = warp * 2 + (lane >> 4);
            float s = red[rowl * 16 + (lane & 15)];
            float q2 = red[512 + rowl * 16 + (lane & 15)];
#pragma unroll
            for (int o = 8; o; o >>= 1) {
                s  += __shfl_xor_sync(FULL_MASK, s, o);
                q2 += __shfl_xor_sync(FULL_MASK, q2, o);
            }
            if ((lane & 15) == 0) {
                float mean = s * (1.f / 512.f);
                float var = q2 * (1.f / 512.f) - mean * mean;
                smean[rowl] = mean;
                sinv[rowl] = rsqrtf(var + 1e-6f);
            }
        }
        __syncthreads();

        // normalize + store (float2, 32B sectors per quad)
#pragma unroll
        for (int m = 0; m < 2; m++) {
#pragma unroll
            for (int rh = 0; rh < 2; rh++) {
                const int rowl = m * 16 + rh * 8 + g;
                const int row = row0 + rowl;
                if (row >= n) continue;
                const float mean = smean[rowl], inv = sinv[rowl];
                float* orow = out + (size_t)row * 512;
#pragma unroll
                for (int q = 0; q < 4; q++) {
                    const int c = warp * 32 + q * 8 + 2 * tig;
                    float2 sc = __ldg((const float2*)(ln3s + c));
                    float2 bc = __ldg((const float2*)(ln3b + c));
                    float2 o;
                    o.x = (d[m][q][2 * rh] - mean) * inv * sc.x + bc.x;
                    o.y = (d[m][q][2 * rh + 1] - mean) * inv * sc.y + bc.y;
                    *(float2*)(orow + c) = o;
                }
            }
        }
    }
}

// ------------------------- host launch --------------------------------------
extern "C" void kernel_launch(void* const* d_in, const int* in_sizes, int n_in,
                              void* d_out, int out_size) {
    const float* h    = (const float*)d_in[0];
    const float* rk   = (const float*)d_in[2];
    const float* Wq   = (const float*)d_in[3];
    const float* bq   = (const float*)d_in[4];
    const float* Wv   = (const float*)d_in[5];
    const float* bv   = (const float*)d_in[6];
    const float* lrs  = (const float*)d_in[7];
    const float* lrb  = (const float*)d_in[8];
    const float* l1s  = (const float*)d_in[9];
    const float* l1b  = (const float*)d_in[10];
    const float* W1   = (const float*)d_in[11];
    const float* b1   = (const float*)d_in[12];
    const float* W2   = (const float*)d_in[13];
    const float* b2   = (const float*)d_in[14];
    const float* W3   = (const float*)d_in[15];
    const float* b3   = (const float*)d_in[16];
    const float* Wk   = (const float*)d_in[17];
    const float* bk   = (const float*)d_in[18];
    const float* ln2s = (const float*)d_in[19];
    const float* ln2b = (const float*)d_in[20];
    const float* Wm   = (const float*)d_in[21];
    const float* bm   = (const float*)d_in[22];
    const float* ln3s = (const float*)d_in[23];
    const float* ln3b = (const float*)d_in[24];
    float* out = (float*)d_out;

    const int n = in_sizes[0] / 512;
    const int nb1 = (n + 127) / 128;
    const int nbm = (n + 31) / 32;

    cudaFuncSetAttribute(k_main_mma, cudaFuncAttributeMaxDynamicSharedMemorySize, SMEM_DYN);

    k_prepF<<<dim3(17, 16), dim3(32, 32)>>>(Wm, Wq, bq, rk);
    k_pass1<<<nb1, 512>>>(h, n);
    k_redS<<<dim3(4, 16), 512>>>(nb1);
    k_smallA<<<1, 512>>>(nb1, Wv, bv, lrs, lrb, l1s, l1b, W1, b1);
    k_smallB2<<<8, 512>>>(W2, b2);
    k_smallC2<<<16, 512>>>(W3, b3);
    k_smallD2<<<9, 512>>>(Wk, bk);
    k_main_mma<<<nbm, 512, SMEM_DYN>>>(h, ln2s, ln2b, bm, ln3s, ln3b, out, n);
}

// round 16
// speedup vs baseline: 1.2911x; 1.2911x over previous
#include <cuda_runtime.h>
#include <cuda_bf16.h>
#include <cuda_fp16.h>
#include <cstdint>

#define FULL_MASK 0xFFFFFFFFu

// ------------------------- device scratch ----------------------------------
__device__ float g_u[512 * 4];
__device__ float g_c1[4];
__device__ float g_dpart[2048 * 4];
__device__ float g_spart[1024 * 2048];
__device__ float g_spart2[16 * 2048];
__device__ float g_x1[512];
__device__ float g_x2[512];
__device__ float g_qk[1024];
__device__ float g_U[512 * 4];
__device__ float g_c[4];
__device__ float g_vals[512];
__device__ float g_sv[4];
__device__ float g_svv[4];
// Wm^T in fp16, chunk-major: [kchunk64][n][kk]
__device__ __half g_WmB[512 * 512];

// ------------------------- helpers -----------------------------------------
__device__ __forceinline__ unsigned long long pack2(float lo, float hi) {
    unsigned long long r;
    asm("mov.b64 %0, {%1, %2};" : "=l"(r) : "f"(lo), "f"(hi));
    return r;
}
__device__ __forceinline__ void unpack2(unsigned long long v, float& lo, float& hi) {
    asm("mov.b64 {%0, %1}, %2;" : "=f"(lo), "=f"(hi) : "l"(v));
}
__device__ __forceinline__ void fma2(unsigned long long& acc,
                                     unsigned long long a, unsigned long long b) {
    asm("fma.rn.f32x2 %0, %1, %2, %0;" : "+l"(acc) : "l"(a), "l"(b));
}
__device__ __forceinline__ float silu_fast(float x) {
    return __fdividef(x, 1.0f + __expf(-x));
}
__device__ __forceinline__ uint32_t smem_u32(const void* p) {
    uint32_t a;
    asm("{ .reg .u64 t; cvta.to.shared.u64 t, %1; cvt.u32.u64 %0, t; }" : "=r"(a) : "l"(p));
    return a;
}
__device__ __forceinline__ uint32_t pkh(__half a, __half b) {
    return (uint32_t)__half_as_ushort(a) | ((uint32_t)__half_as_ushort(b) << 16);
}
__device__ __forceinline__ void cp16(uint32_t dst, const void* src) {
    asm volatile("cp.async.cg.shared.global [%0], [%1], 16;" :: "r"(dst), "l"(src));
}
__device__ __forceinline__ void ldsm4(uint32_t& r0, uint32_t& r1, uint32_t& r2,
                                      uint32_t& r3, uint32_t addr) {
    asm volatile("ldmatrix.sync.aligned.m8n8.x4.shared.b16 {%0,%1,%2,%3}, [%4];"
                 : "=r"(r0), "=r"(r1), "=r"(r2), "=r"(r3) : "r"(addr));
}
__device__ __forceinline__ void mma_f16(float& d0, float& d1, float& d2, float& d3,
                                        uint32_t a0, uint32_t a1, uint32_t a2, uint32_t a3,
                                        uint32_t b0, uint32_t b1) {
    asm volatile(
        "mma.sync.aligned.m16n8k16.row.col.f32.f16.f16.f32 "
        "{%0,%1,%2,%3}, {%4,%5,%6,%7}, {%8,%9}, {%0,%1,%2,%3};"
        : "+f"(d0), "+f"(d1), "+f"(d2), "+f"(d3)
        : "r"(a0), "r"(a1), "r"(a2), "r"(a3), "r"(b0), "r"(b1));
}

// ------------------------- kernel: prep fused (Wm fp16 + Wq/rk fold) --------
__global__ void __launch_bounds__(1024) k_prepF(const float* __restrict__ Wm,
                                                const float* __restrict__ Wq,
                                                const float* __restrict__ bq,
                                                const float* __restrict__ rk) {
    if (blockIdx.x == 16) {
        if (blockIdx.y == 0) {
            int t = threadIdx.y * 32 + threadIdx.x;
            if (t < 512) {
                float u[4];
#pragma unroll
                for (int r = 0; r < 4; r++) {
                    float s = 0.f;
#pragma unroll
                    for (int d = 0; d < 4; d++) s += Wq[t * 16 + 4 * r + d] * rk[4 * r + d];
                    u[r] = s;
                }
                ((float4*)g_u)[t] = make_float4(u[0], u[1], u[2], u[3]);
                if (t < 4) {
                    float s = 0.f;
#pragma unroll
                    for (int d = 0; d < 4; d++) s += bq[4 * t + d] * rk[4 * t + d];
                    g_c1[t] = s;
                }
            }
        }
        return;
    }
    __shared__ float tile[32][33];
    int tx = threadIdx.x, ty = threadIdx.y;
    tile[ty][tx] = Wm[(blockIdx.y * 32 + ty) * 512 + blockIdx.x * 32 + tx];
    __syncthreads();
    int n = blockIdx.x * 32 + ty;
    int k = blockIdx.y * 32 + tx;
    float v = tile[tx][ty];
    size_t idx = ((size_t)(k >> 6) * 512 + n) * 64 + (k & 63);
    g_WmB[idx] = __float2half(v);
}

// ------------------------- kernel: fused pass 1 -----------------------------
__global__ void __launch_bounds__(512) k_pass1(const float* __restrict__ h, int n) {
    __shared__ float4 se[128];
    __shared__ float sD[16][4];
    const int tid = threadIdx.x, warp = tid >> 5, lane = tid & 31;
    const int base = blockIdx.x * 128;

    const float c10 = g_c1[0], c11 = g_c1[1], c12 = g_c1[2], c13 = g_c1[3];
    float d0 = 0.f, d1 = 0.f, d2 = 0.f, d3 = 0.f;

#pragma unroll
    for (int rr = 0; rr < 8; rr++) {
        const int rloc = warp * 8 + rr;
        const int row = base + rloc;
        const bool valid = (row < n);
        const float* hr = h + (size_t)row * 512;

        float l0 = 0.f, l1 = 0.f, l2 = 0.f, l3 = 0.f;
        if (valid) {
#pragma unroll
            for (int t = 0; t < 16; t++) {
                int k = lane + 32 * t;
                float hk = __ldg(hr + k);
                float4 u = __ldg((const float4*)g_u + k);
                l0 += hk * u.x; l1 += hk * u.y; l2 += hk * u.z; l3 += hk * u.w;
            }
        }
#pragma unroll
        for (int o = 16; o; o >>= 1) {
            l0 += __shfl_xor_sync(FULL_MASK, l0, o);
            l1 += __shfl_xor_sync(FULL_MASK, l1, o);
            l2 += __shfl_xor_sync(FULL_MASK, l2, o);
            l3 += __shfl_xor_sync(FULL_MASK, l3, o);
        }
        if (lane == 0) {
            float m = valid ? 1.f : 0.f;
            float e0 = m * __expf(0.5f * (l0 + c10));
            float e1 = m * __expf(0.5f * (l1 + c11));
            float e2 = m * __expf(0.5f * (l2 + c12));
            float e3 = m * __expf(0.5f * (l3 + c13));
            se[rloc] = make_float4(e0, e1, e2, e3);
            d0 += e0; d1 += e1; d2 += e2; d3 += e3;
        }
    }
    if (lane == 0) {
        sD[warp][0] = d0; sD[warp][1] = d1; sD[warp][2] = d2; sD[warp][3] = d3;
    }
    __syncthreads();
    if (warp == 0 && lane < 4) {
        float s = 0.f;
#pragma unroll
        for (int w = 0; w < 16; w++) s += sD[w][lane];
        g_dpart[blockIdx.x * 4 + lane] = s;
    }

    const int c = tid;
    int lim = n - base; if (lim > 128) lim = 128;
    unsigned long long a01 = pack2(0.f, 0.f), a23 = pack2(0.f, 0.f);
    const float* hc = h + (size_t)base * 512 + c;
#pragma unroll 4
    for (int i = 0; i < lim; i++) {
        float4 e = se[i];
        float hv = __ldg(hc + (size_t)i * 512);
        unsigned long long hd = pack2(hv, hv);
        fma2(a01, hd, pack2(e.x, e.y));
        fma2(a23, hd, pack2(e.z, e.w));
    }
    float s0, s1, s2, s3;
    unpack2(a01, s0, s1);
    unpack2(a23, s2, s3);
    float* dst = g_spart + (size_t)blockIdx.x * 2048;
    dst[0 * 512 + c] = s0;
    dst[1 * 512 + c] = s1;
    dst[2 * 512 + c] = s2;
    dst[3 * 512 + c] = s3;
}

// ------------------------- kernel: S partial reduction (grid 4x16) ----------
__global__ void __launch_bounds__(512) k_redS(int nb) {
    const int col = blockIdx.x * 512 + threadIdx.x;
    const int chunk = (nb + 15) / 16;
    int i0 = blockIdx.y * chunk;
    int i1 = i0 + chunk; if (i1 > nb) i1 = nb;
    float s = 0.f;
    const float* src = g_spart + col;
#pragma unroll 4
    for (int i = i0; i < i1; i++) s += src[(size_t)i * 2048];
    g_spart2[blockIdx.y * 2048 + col] = s;
}

// ------------------------- kernel: smallA (S/D finalize, LN chain, x1) ------
__global__ void __launch_bounds__(512) k_smallA(int nb,
        const float* __restrict__ Wv,  const float* __restrict__ bv,
        const float* __restrict__ lrs, const float* __restrict__ lrb,
        const float* __restrict__ l1s, const float* __restrict__ l1b,
        const float* __restrict__ W1,  const float* __restrict__ b1) {
    __shared__ float sS[4 * 512];
    __shared__ float sDv[4];
    __shared__ float sNum[16];
    __shared__ float sr16[16];
    const int tid = threadIdx.x, warp = tid >> 5, lane = tid & 31;

#pragma unroll
    for (int r = 0; r < 4; r++) {
        int col = r * 512 + tid;
        float s = 0.f;
#pragma unroll
        for (int j = 0; j < 16; j++) s += g_spart2[j * 2048 + col];
        sS[col] = s;
    }
    if (warp < 4) {
        float s = 0.f;
        for (int i = lane; i < nb; i += 32) s += g_dpart[i * 4 + warp];
#pragma unroll
        for (int o = 16; o; o >>= 1) s += __shfl_xor_sync(FULL_MASK, s, o);
        if (lane == 0) sDv[warp] = s;
    }
    __syncthreads();

    {
        const int r = warp >> 2;
        float s = 0.f;
        for (int c = lane; c < 512; c += 32) s += sS[r * 512 + c] * Wv[c * 16 + warp];
#pragma unroll
        for (int o = 16; o; o >>= 1) s += __shfl_xor_sync(FULL_MASK, s, o);
        if (lane == 0) sNum[warp] = s;
    }
    __syncthreads();

    if (tid == 0) {
        float reg[16];
#pragma unroll
        for (int i = 0; i < 16; i++) reg[i] = sNum[i] / sDv[i >> 2] + bv[i];
#pragma unroll
        for (int pass = 0; pass < 2; pass++) {
            const float* sc = pass ? l1s : lrs;
            const float* bc = pass ? l1b : lrb;
            float m = 0.f;
            for (int i = 0; i < 16; i++) m += reg[i];
            m *= (1.f / 16.f);
            float v = 0.f;
            for (int i = 0; i < 16; i++) { float d = reg[i] - m; v += d * d; }
            v *= (1.f / 16.f);
            float inv = rsqrtf(v + 1e-6f);
            for (int i = 0; i < 16; i++) reg[i] = (reg[i] - m) * inv * sc[i] + bc[i];
        }
        for (int i = 0; i < 16; i++) sr16[i] = reg[i];
    }
    __syncthreads();

    float s = b1[tid];
#pragma unroll
    for (int i = 0; i < 16; i++) s += sr16[i] * W1[i * 512 + tid];
    g_x1[tid] = s / (1.f + expf(-s));
}

// ------------------------- kernel: smallB2 — x2 (grid 8) --------------------
__global__ void __launch_bounds__(512) k_smallB2(const float* __restrict__ W2,
                                                 const float* __restrict__ b2) {
    __shared__ float sx1[512];
    __shared__ float red[512];
    const int t = threadIdx.x;
    sx1[t] = g_x1[t];
    __syncthreads();
    const int j = blockIdx.x * 64 + (t & 63);
    const int ks = t >> 6;
    float s = 0.f;
    const float* w = W2 + (size_t)(ks * 64) * 512 + j;
    const float* xs = sx1 + ks * 64;
#pragma unroll 16
    for (int k = 0; k < 64; k++) s += xs[k] * __ldg(w + (size_t)k * 512);
    red[t] = s;
    __syncthreads();
    if (t < 64) {
        float v = b2[blockIdx.x * 64 + t];
#pragma unroll
        for (int i = 0; i < 8; i++) v += red[i * 64 + t];
        g_x2[blockIdx.x * 64 + t] = v / (1.f + expf(-v));
    }
}

// ------------------------- kernel: smallC2 — qk (grid 16) -------------------
__global__ void __launch_bounds__(512) k_smallC2(const float* __restrict__ W3,
                                                 const float* __restrict__ b3) {
    __shared__ float sx2[512];
    __shared__ float red[512];
    const int t = threadIdx.x;
    sx2[t] = g_x2[t];
    __syncthreads();
    const int j = blockIdx.x * 64 + (t & 63);
    const int ks = t >> 6;
    float s = 0.f;
    const float* w = W3 + (size_t)(ks * 64) * 1024 + j;
    const float* xs = sx2 + ks * 64;
#pragma unroll 16
    for (int k = 0; k < 64; k++) s += xs[k] * __ldg(w + (size_t)k * 1024);
    red[t] = s;
    __syncthreads();
    if (t < 64) {
        float v = b3[blockIdx.x * 64 + t];
#pragma unroll
        for (int i = 0; i < 8; i++) v += red[i * 64 + t];
        g_qk[blockIdx.x * 64 + t] = v;
    }
}

// ------------------------- kernel: smallD2 — U fold + stats (grid 9) --------
__global__ void __launch_bounds__(512) k_smallD2(const float* __restrict__ Wk,
                                                 const float* __restrict__ bk) {
    const int t = threadIdx.x, warp = t >> 5, lane = t & 31;
    if (blockIdx.x == 8) {
        g_vals[t] = g_qk[512 + t];
        if (warp < 4) {
            float s = 0.f, sv = 0.f, svv = 0.f;
            for (int d = lane; d < 128; d += 32) {
                float qv = g_qk[warp * 128 + d];
                s += bk[warp * 128 + d] * qv;
                float v = g_qk[512 + warp * 128 + d];
                sv += v; svv += v * v;
            }
#pragma unroll
            for (int o = 16; o; o >>= 1) {
                s   += __shfl_xor_sync(FULL_MASK, s, o);
                sv  += __shfl_xor_sync(FULL_MASK, sv, o);
                svv += __shfl_xor_sync(FULL_MASK, svv, o);
            }
            if (lane == 0) {
                g_c[warp] = s * rsqrtf(128.f);
                g_sv[warp] = sv;
                g_svv[warp] = svv;
            }
        }
        return;
    }
    __shared__ float sqk[1024];
    __shared__ float red[512];
    sqk[t] = g_qk[t];
    sqk[t + 512] = g_qk[t + 512];
    __syncthreads();
    const int r = blockIdx.x * 64 + (t >> 3);
    const int p = t & 7, head = p >> 1, half = p & 1;
    const float4* wr = (const float4*)(Wk + (size_t)r * 512 + head * 128 + half * 64);
    const float* qv = sqk + head * 128 + half * 64;
    float s = 0.f;
#pragma unroll
    for (int d4 = 0; d4 < 16; d4++) {
        float4 w = __ldg(wr + d4);
        s += w.x * qv[4 * d4 + 0] + w.y * qv[4 * d4 + 1]
           + w.z * qv[4 * d4 + 2] + w.w * qv[4 * d4 + 3];
    }
    red[t] = s;
    __syncthreads();
    if (t < 256) {
        const int rr = t >> 2, hh = t & 3;
        float v = red[rr * 8 + hh * 2] + red[rr * 8 + hh * 2 + 1];
        g_U[(blockIdx.x * 64 + rr) * 4 + hh] = v * rsqrtf(128.f);
    }
}

// ------------------------- kernel: main (HMMA fp16, whole-K A tile) ---------
// Block: 64 rows x 512 cols, 512 threads (16 warps, warp tile 32x64).
// A (h2n fp16, full K=512) built once in smem; mainloop pure B-load + MMA over
// 8 chunks of Kc=64 (B double-buffered). Register epilogue, no D staging.
#define BSTRIDE 144
#define B_BUF_STRIDE 73728
#define ASTRIDE 1040
#define OFF_A 147456
#define OFF_SA 214016
#define OFF_MEAN 215040
#define OFF_INV 215296
#define SMEM_DYN 215552

__device__ __forceinline__ void loadB_async(uint32_t base32, int buf, int kc, int tid) {
    const __half* sH = g_WmB + (size_t)kc * 32768;
    uint32_t bh = base32 + buf * B_BUF_STRIDE;
#pragma unroll
    for (int j = 0; j < 8; j++) {
        int f = j * 512 + tid;
        uint32_t doff = (uint32_t)((f >> 3) * BSTRIDE + (f & 7) * 16);
        cp16(bh + doff, sH + f * 8);
    }
}

__global__ void __launch_bounds__(512, 1) k_main_mma(const float* __restrict__ h,
        const float* __restrict__ ln2s, const float* __restrict__ ln2b,
        const float* __restrict__ bm,
        const float* __restrict__ ln3s, const float* __restrict__ ln3b,
        float* __restrict__ out, int n) {
    extern __shared__ char sb[];
    const uint32_t base32 = smem_u32(sb);
    float* sa    = (float*)(sb + OFF_SA);
    float* smean = (float*)(sb + OFF_MEAN);
    float* sinv  = (float*)(sb + OFF_INV);
    float* red   = (float*)sb;   // epilogue cross-warp reduce (B region)

    const int tid = threadIdx.x, warp = tid >> 5, lane = tid & 31;
    const int row0 = blockIdx.x * 64;

    // ---------- Phase A: per-row softmax + closed-form LN2 stats ------------
    {
        const float c0 = g_c[0], c1 = g_c[1], c2 = g_c[2], c3 = g_c[3];
        const float sv0 = g_sv[0], sv1 = g_sv[1], sv2 = g_sv[2], sv3 = g_sv[3];
        const float w0 = g_svv[0], w1 = g_svv[1], w2 = g_svv[2], w3 = g_svv[3];
#pragma unroll
        for (int rr = 0; rr < 4; rr++) {
            const int rloc = warp * 4 + rr;
            const int row = row0 + rloc;
            const bool valid = (row < n);
            const float* hr = h + (size_t)row * 512;
            float l0 = 0.f, l1 = 0.f, l2 = 0.f, l3 = 0.f;
            float hv0 = 0.f, hv1 = 0.f, hv2 = 0.f, hv3 = 0.f;
            float sh = 0.f, sq = 0.f;
            if (valid) {
#pragma unroll
                for (int t = 0; t < 16; t++) {
                    int k = lane + 32 * t;
                    float hk = __ldg(hr + k);
                    float4 u = __ldg((const float4*)g_U + k);
                    float vk = __ldg(g_vals + k);
                    l0 += hk * u.x; l1 += hk * u.y; l2 += hk * u.z; l3 += hk * u.w;
                    float p = hk * vk;
                    if (t < 4) hv0 += p; else if (t < 8) hv1 += p;
                    else if (t < 12) hv2 += p; else hv3 += p;
                    sh += hk; sq += hk * hk;
                }
            }
#pragma unroll
            for (int o = 16; o; o >>= 1) {
                l0 += __shfl_xor_sync(FULL_MASK, l0, o);
                l1 += __shfl_xor_sync(FULL_MASK, l1, o);
                l2 += __shfl_xor_sync(FULL_MASK, l2, o);
                l3 += __shfl_xor_sync(FULL_MASK, l3, o);
                hv0 += __shfl_xor_sync(FULL_MASK, hv0, o);
                hv1 += __shfl_xor_sync(FULL_MASK, hv1, o);
                hv2 += __shfl_xor_sync(FULL_MASK, hv2, o);
                hv3 += __shfl_xor_sync(FULL_MASK, hv3, o);
                sh += __shfl_xor_sync(FULL_MASK, sh, o);
                sq += __shfl_xor_sync(FULL_MASK, sq, o);
            }
            if (lane == 0) {
                if (valid) {
                    l0 += c0; l1 += c1; l2 += c2; l3 += c3;
                    float mx = fmaxf(fmaxf(l0, l1), fmaxf(l2, l3));
                    float e0 = __expf(l0 - mx), e1 = __expf(l1 - mx);
                    float e2 = __expf(l2 - mx), e3 = __expf(l3 - mx);
                    float si = __fdividef(1.f, e0 + e1 + e2 + e3);
                    float a0 = e0 * si, a1 = e1 * si, a2 = e2 * si, a3 = e3 * si;
                    float sum = sh + a0 * sv0 + a1 * sv1 + a2 * sv2 + a3 * sv3;
                    float ssq = sq + 2.f * (a0 * hv0 + a1 * hv1 + a2 * hv2 + a3 * hv3)
                              + a0 * a0 * w0 + a1 * a1 * w1 + a2 * a2 * w2 + a3 * a3 * w3;
                    float mean = sum * (1.f / 512.f);
                    float var = ssq * (1.f / 512.f) - mean * mean;
                    sa[rloc * 4 + 0] = a0; sa[rloc * 4 + 1] = a1;
                    sa[rloc * 4 + 2] = a2; sa[rloc * 4 + 3] = a3;
                    smean[rloc] = mean;
                    sinv[rloc] = rsqrtf(var + 1e-6f);
                } else {
                    sa[rloc * 4 + 0] = 0.f; sa[rloc * 4 + 1] = 0.f;
                    sa[rloc * 4 + 2] = 0.f; sa[rloc * 4 + 3] = 0.f;
                    smean[rloc] = 0.f; sinv[rloc] = 0.f;
                }
            }
        }
    }
    __syncthreads();

    // ---------- Build full A tile (h2n fp16, K=512) --------------------------
    {
        const int arow = tid >> 3, kq = tid & 7;
        const bool avalid = (row0 + arow < n);
        const float* harow = h + (size_t)(row0 + arow) * 512;
        const float mean = smean[arow], inv = sinv[arow];
        char* arb = sb + OFF_A + arow * ASTRIDE;
#pragma unroll
        for (int kc = 0; kc < 8; kc++) {
            const int kg = kc * 64 + kq * 8;
            const float ah = sa[arow * 4 + (kc >> 1)];
            float4 hv0 = make_float4(0.f, 0.f, 0.f, 0.f), hv1 = hv0;
            if (avalid) {
                hv0 = __ldg((const float4*)(harow + kg));
                hv1 = __ldg((const float4*)(harow + kg + 4));
            }
            float4 vA = __ldg((const float4*)(g_vals + kg));
            float4 vB = __ldg((const float4*)(g_vals + kg + 4));
            float4 sA = __ldg((const float4*)(ln2s + kg));
            float4 sB = __ldg((const float4*)(ln2s + kg + 4));
            float4 bA = __ldg((const float4*)(ln2b + kg));
            float4 bB = __ldg((const float4*)(ln2b + kg + 4));
            float hx[8] = {hv0.x, hv0.y, hv0.z, hv0.w, hv1.x, hv1.y, hv1.z, hv1.w};
            float vx[8] = {vA.x, vA.y, vA.z, vA.w, vB.x, vB.y, vB.z, vB.w};
            float sx[8] = {sA.x, sA.y, sA.z, sA.w, sB.x, sB.y, sB.z, sB.w};
            float bx[8] = {bA.x, bA.y, bA.z, bA.w, bB.x, bB.y, bB.z, bB.w};
            uint32_t w[4];
#pragma unroll
            for (int p = 0; p < 4; p++) {
                float x0 = avalid ? ((hx[2 * p] + ah * vx[2 * p] - mean) * inv * sx[2 * p] + bx[2 * p]) : 0.f;
                float x1 = avalid ? ((hx[2 * p + 1] + ah * vx[2 * p + 1] - mean) * inv * sx[2 * p + 1] + bx[2 * p + 1]) : 0.f;
                w[p] = pkh(__float2half(x0), __float2half(x1));
            }
            *(uint4*)(arb + kc * 128 + kq * 16) = make_uint4(w[0], w[1], w[2], w[3]);
        }
    }

    // ---------- GEMM pipeline (8 chunks of Kc=64, B double buffer) -----------
    const int rowg = warp >> 3, colg = warp & 7;
    const int g = lane >> 2, tig = lane & 3;

    const uint32_t aoff = (uint32_t)((lane & 15) * ASTRIDE + (lane >> 4) * 16);
    const uint32_t boff = (uint32_t)(((((lane >> 4) << 3) + (lane & 7)) * BSTRIDE)
                                     + ((lane >> 3) & 1) * 16);
    const uint32_t aAddr = base32 + OFF_A + (uint32_t)(rowg * 32) * ASTRIDE + aoff;
    const uint32_t bAddr = base32 + (uint32_t)(colg * 64) * BSTRIDE + boff;

    float d0[8][4], d1[8][4];
#pragma unroll
    for (int nt = 0; nt < 8; nt++)
#pragma unroll
        for (int e = 0; e < 4; e++) { d0[nt][e] = 0.f; d1[nt][e] = 0.f; }

    loadB_async(base32, 0, 0, tid);
    asm volatile("cp.async.commit_group;" ::: "memory");
    asm volatile("cp.async.wait_group 0;" ::: "memory");
    __syncthreads();   // A tile + B chunk 0 ready

    for (int kc = 0; kc < 8; kc++) {
        const int buf = kc & 1, nxt = buf ^ 1;
        if (kc < 7) {
            loadB_async(base32, nxt, kc + 1, tid);
            asm volatile("cp.async.commit_group;" ::: "memory");
        }

        {
            const uint32_t aB = aAddr + (uint32_t)(kc * 128);
            const uint32_t bB = bAddr + (uint32_t)(buf * B_BUF_STRIDE);
#pragma unroll
            for (int ks = 0; ks < 4; ks++) {
                const uint32_t ka = aB + ks * 32;
                uint32_t ah[8];
                ldsm4(ah[0], ah[1], ah[2], ah[3], ka);
                ldsm4(ah[4], ah[5], ah[6], ah[7], ka + 16 * ASTRIDE);
                const uint32_t kb = bB + ks * 32;
#pragma unroll
                for (int np = 0; np < 4; np++) {
                    uint32_t bh[4];
                    const uint32_t bt = kb + (uint32_t)(np * 16 * BSTRIDE);
                    ldsm4(bh[0], bh[1], bh[2], bh[3], bt);
#pragma unroll
                    for (int hf = 0; hf < 2; hf++) {
                        const int nt = 2 * np + hf;
                        const uint32_t b0 = bh[2 * hf], b1 = bh[2 * hf + 1];
                        mma_f16(d0[nt][0], d0[nt][1], d0[nt][2], d0[nt][3],
                                ah[0], ah[1], ah[2], ah[3], b0, b1);
                        mma_f16(d1[nt][0], d1[nt][1], d1[nt][2], d1[nt][3],
                                ah[4], ah[5], ah[6], ah[7], b0, b1);
                    }
                }
            }
        }

        asm volatile("cp.async.wait_group 0;" ::: "memory");
        __syncthreads();
    }

    // ---------- register epilogue: y, LN3, write -----------------------------
    {
        // rows: rowg*32 + {g, g+8, g+16, g+24}; cols: colg*64 + nt*8 + 2*tig +{0,1}
        float rsum[4], rsq[4];
#pragma unroll
        for (int i = 0; i < 4; i++) { rsum[i] = 0.f; rsq[i] = 0.f; }
#pragma unroll
        for (int nt = 0; nt < 8; nt++) {
            const int c = colg * 64 + nt * 8 + 2 * tig;
            float2 bmv = __ldg((const float2*)(bm + c));
            float* dp[4] = {&d0[nt][0], &d0[nt][2], &d1[nt][0], &d1[nt][2]};
#pragma unroll
            for (int rr = 0; rr < 4; rr++) {
                const int rowl = rowg * 32 + rr * 8 + g;
                float2 a2 = __half22float2(
                    *(const __half2*)(sb + OFF_A + rowl * ASTRIDE + c * 2));
                float y0 = a2.x + silu_fast(dp[rr][0] + bmv.x);
                float y1 = a2.y + silu_fast(dp[rr][1] + bmv.y);
                dp[rr][0] = y0;
                dp[rr][1] = y1;
                rsum[rr] += y0 + y1;
                rsq[rr] += y0 * y0 + y1 * y1;
            }
        }
        // reduce across the 4 tig lanes (same rows, different cols)
#pragma unroll
        for (int i = 0; i < 4; i++) {
            rsum[i] += __shfl_xor_sync(FULL_MASK, rsum[i], 1);
            rsum[i] += __shfl_xor_sync(FULL_MASK, rsum[i], 2);
            rsq[i]  += __shfl_xor_sync(FULL_MASK, rsq[i], 1);
            rsq[i]  += __shfl_xor_sync(FULL_MASK, rsq[i], 2);
        }
        if (tig == 0) {
#pragma unroll
            for (int i = 0; i < 4; i++) {
                const int rowl = rowg * 32 + i * 8 + g;
                red[rowl * 8 + colg] = rsum[i];
                red[512 + rowl * 8 + colg] = rsq[i];
            }
        }
        __syncthreads();

        // per-row stats: warp w handles rows 4w..4w+3 (8 lanes each)
        {
            const int rowl = warp * 4 + (lane >> 3);
            const int e = lane & 7;
            float s = red[rowl * 8 + e];
            float q2 = red[512 + rowl * 8 + e];
#pragma unroll
            for (int o = 4; o; o >>= 1) {
                s  += __shfl_xor_sync(FULL_MASK, s, o);
                q2 += __shfl_xor_sync(FULL_MASK, q2, o);
            }
            if (e == 0) {
                float mean = s * (1.f / 512.f);
                float var = q2 * (1.f / 512.f) - mean * mean;
                smean[rowl] = mean;
                sinv[rowl] = rsqrtf(var + 1e-6f);
            }
        }
        __syncthreads();

        // normalize + store (float2)
#pragma unroll
        for (int rr = 0; rr < 4; rr++) {
            const int rowl = rowg * 32 + rr * 8 + g;
            const int row = row0 + rowl;
            if (row >= n) continue;
            const float mean = smean[rowl], inv = sinv[rowl];
            float* orow = out + (size_t)row * 512;
            float* dsrc0 = (rr < 2) ? &d0[0][0] : &d1[0][0];
#pragma unroll
            for (int nt = 0; nt < 8; nt++) {
                const int c = colg * 64 + nt * 8 + 2 * tig;
                float2 sc = __ldg((const float2*)(ln3s + c));
                float2 bc = __ldg((const float2*)(ln3b + c));
                const float* dv = dsrc0 + nt * 4 + (rr & 1) * 2;
                float2 o;
                o.x = (dv[0] - mean) * inv * sc.x + bc.x;
                o.y = (dv[1] - mean) * inv * sc.y + bc.y;
                *(float2*)(orow + c) = o;
            }
        }
    }
}

// ------------------------- host launch --------------------------------------
extern "C" void kernel_launch(void* const* d_in, const int* in_sizes, int n_in,
                              void* d_out, int out_size) {
    const float* h    = (const float*)d_in[0];
    const float* rk   = (const float*)d_in[2];
    const float* Wq   = (const float*)d_in[3];
    const float* bq   = (const float*)d_in[4];
    const float* Wv   = (const float*)d_in[5];
    const float* bv   = (const float*)d_in[6];
    const float* lrs  = (const float*)d_in[7];
    const float* lrb  = (const float*)d_in[8];
    const float* l1s  = (const float*)d_in[9];
    const float* l1b  = (const float*)d_in[10];
    const float* W1   = (const float*)d_in[11];
    const float* b1   = (const float*)d_in[12];
    const float* W2   = (const float*)d_in[13];
    const float* b2   = (const float*)d_in[14];
    const float* W3   = (const float*)d_in[15];
    const float* b3   = (const float*)d_in[16];
    const float* Wk   = (const float*)d_in[17];
    const float* bk   = (const float*)d_in[18];
    const float* ln2s = (const float*)d_in[19];
    const float* ln2b = (const float*)d_in[20];
    const float* Wm   = (const float*)d_in[21];
    const float* bm   = (const float*)d_in[22];
    const float* ln3s = (const float*)d_in[23];
    const float* ln3b = (const float*)d_in[24];
    float* out = (float*)d_out;

    const int n = in_sizes[0] / 512;
    const int nb1 = (n + 127) / 128;
    const int nbm = (n + 63) / 64;

    cudaFuncSetAttribute(k_main_mma, cudaFuncAttributeMaxDynamicSharedMemorySize, SMEM_DYN);

    k_prepF<<<dim3(17, 16), dim3(32, 32)>>>(Wm, Wq, bq, rk);
    k_pass1<<<nb1, 512>>>(h, n);
    k_redS<<<dim3(4, 16), 512>>>(nb1);
    k_smallA<<<1, 512>>>(nb1, Wv, bv, lrs, lrb, l1s, l1b, W1, b1);
    k_smallB2<<<8, 512>>>(W2, b2);
    k_smallC2<<<16, 512>>>(W3, b3);
    k_smallD2<<<9, 512>>>(Wk, bk);
    k_main_mma<<<nbm, 512, SMEM_DYN>>>(h, ln2s, ln2b, bm, ln3s, ln3b, out, n);
}